// round 5
// baseline (speedup 1.0000x reference)
#include <cuda_runtime.h>
#include <cuda_bf16.h>
#include <math.h>
#include <stdint.h>

// ---------------------------------------------------------------------------
// BoundaryAwareViT — fused-FFN megakernel + LN fusion + im2col-in-GEMM.
// B=32, IMG=512, P=16, D=256, DEPTH=8, G=32, N=1024, DQ=32, DF=1024, M=32768
// ---------------------------------------------------------------------------

#define Mtok  32768
#define Dd    256
#define DFf   1024
#define Nn    1024
#define QKVW  320        // 32 q + 32 k + 256 v

__device__ float g_h   [Mtok * Dd];
__device__ float g_xn  [Mtok * Dd];
__device__ float g_lap [Mtok * Dd];
__device__ float g_qkv [Mtok * QKVW];
__device__ float g_att [Mtok * 64];
__device__ float g_wpT [Dd * Dd];          // patch weight [n][k], rounded
__device__ float g_weT [Dd * Dd];          // edge weight transposed [n][k]
__device__ float g_wqkvT[8 * QKVW * Dd];   // [l][c][k]
__device__ float g_bqkv [8 * QKVW];
__device__ float g_w1T [8 * DFf * Dd];     // [l][1024][256]
__device__ float g_w2T [8 * Dd * DFf];     // [l][256][1024]

__device__ __forceinline__ uint32_t f2tf(float f) {
    uint32_t u;
    asm("cvt.rna.tf32.f32 %0, %1;" : "=r"(u) : "f"(f));
    return u;
}
__device__ __forceinline__ float rndtf(float f) { return __uint_as_float(f2tf(f)); }

// ---------------------------------------------------------------------------
// cp.async / ldmatrix helpers
// ---------------------------------------------------------------------------
__device__ __forceinline__ void cp16(float* s, const float* g) {
    uint32_t sa = (uint32_t)__cvta_generic_to_shared(s);
    asm volatile("cp.async.cg.shared.global [%0], [%1], 16;" :: "r"(sa), "l"(g));
}
__device__ __forceinline__ void cp16z(float* s, const float* g, bool valid) {
    uint32_t sa = (uint32_t)__cvta_generic_to_shared(s);
    int sz = valid ? 16 : 0;
    asm volatile("cp.async.cg.shared.global [%0], [%1], 16, %2;" :: "r"(sa), "l"(g), "r"(sz));
}
#define CP_COMMIT() asm volatile("cp.async.commit_group;" ::: "memory")
#define CP_WAIT1()  asm volatile("cp.async.wait_group 1;" ::: "memory")
#define CP_WAIT0()  asm volatile("cp.async.wait_group 0;" ::: "memory")

__device__ __forceinline__ void ldsm4(uint32_t& r0, uint32_t& r1, uint32_t& r2, uint32_t& r3,
                                      uint32_t addr) {
    asm volatile("ldmatrix.sync.aligned.m8n8.x4.shared.b16 {%0,%1,%2,%3}, [%4];"
                 : "=r"(r0), "=r"(r1), "=r"(r2), "=r"(r3) : "r"(addr));
}
#define MMA_TF32(acc, a, b0, b1)                                               \
    asm volatile("mma.sync.aligned.m16n8k8.row.col.f32.tf32.tf32.f32 "         \
                 "{%0,%1,%2,%3}, {%4,%5,%6,%7}, {%8,%9}, {%0,%1,%2,%3};"       \
                 : "+f"(acc[0]), "+f"(acc[1]), "+f"(acc[2]), "+f"(acc[3])      \
                 : "r"(a[0]), "r"(a[1]), "r"(a[2]), "r"(a[3]), "r"(b0), "r"(b1))

// ---------------------------------------------------------------------------
// prep_all: wpT round-copy (blocks 0..255), weT transpose (256..319),
//           qkv pack (320..2879)
// ---------------------------------------------------------------------------
__global__ void prep_all_k(const float* __restrict__ wp, const float* __restrict__ we,
                           const float* __restrict__ wq, const float* __restrict__ wk,
                           const float* __restrict__ wv, const float* __restrict__ bq,
                           const float* __restrict__ bk, const float* __restrict__ bv,
                           float* __restrict__ wpT, float* __restrict__ weT,
                           float* __restrict__ wqkvT, float* __restrict__ bqkv)
{
    int bx = blockIdx.x, tid = threadIdx.x;
    if (bx < 256) {
        int i = bx * 256 + tid;
        wpT[i] = rndtf(wp[i]);
    } else if (bx < 320) {
        __shared__ float t[32][33];
        int tile = bx - 256;
        int r0 = (tile >> 3) * 32, c0 = (tile & 7) * 32;
        int tx = tid & 31, ty = tid >> 5;
        #pragma unroll
        for (int i = 0; i < 32; i += 8)
            t[ty + i][tx] = we[(r0 + ty + i) * 256 + c0 + tx];
        __syncthreads();
        #pragma unroll
        for (int i = 0; i < 32; i += 8)
            weT[(c0 + ty + i) * 256 + r0 + tx] = rndtf(t[tx][ty + i]);
    } else {
        int idx = (bx - 320) * 256 + tid;   // 8*320*256
        int k  = idx & 255;
        int c  = (idx >> 8) % QKVW;
        int l  = idx / (QKVW * 256);
        float val;
        if (c < 32)      val = wq[(l * 256 + k) * 32 + c];
        else if (c < 64) val = wk[(l * 256 + k) * 32 + (c - 32)];
        else             val = wv[(l * 256 + k) * 256 + (c - 64)];
        wqkvT[idx] = rndtf(val);
        if (idx < 8 * QKVW) {
            int l2 = idx / QKVW, c2 = idx % QKVW;
            bqkv[idx] = (c2 < 32) ? bq[l2 * 32 + c2]
                      : (c2 < 64) ? bk[l2 * 32 + c2 - 32]
                                  : bv[l2 * 256 + c2 - 64];
        }
    }
}

// big weight transposes: z<8 -> w1 [256x1024]->[1024x256]; z>=8 -> w2
__global__ void transpose_big_k(const float* __restrict__ w1, const float* __restrict__ w2,
                                float* __restrict__ w1T, float* __restrict__ w2T)
{
    __shared__ float t[32][33];
    int z = blockIdx.z;
    const float* src; float* dst; int R, C, l;
    if (z < 8) { l = z;     src = w1 + (size_t)l * 256 * 1024; dst = w1T + (size_t)l * 256 * 1024; R = 256;  C = 1024; if (blockIdx.y >= 8)  return; }
    else       { l = z - 8; src = w2 + (size_t)l * 256 * 1024; dst = w2T + (size_t)l * 256 * 1024; R = 1024; C = 256;  if (blockIdx.x >= 8)  return; }
    int c0 = blockIdx.x * 32, r0 = blockIdx.y * 32;
    int tx = threadIdx.x & 31, ty = threadIdx.x >> 5;
    #pragma unroll
    for (int i = 0; i < 32; i += 8)
        t[ty + i][tx] = src[(size_t)(r0 + ty + i) * C + c0 + tx];
    __syncthreads();
    #pragma unroll
    for (int i = 0; i < 32; i += 8)
        dst[(size_t)(c0 + ty + i) * R + r0 + tx] = rndtf(t[tx][ty + i]);
}

// ---------------------------------------------------------------------------
// Laplacian (pre-rounded for edge GEMM)
// ---------------------------------------------------------------------------
__global__ void lap_k(const float* __restrict__ t, float* __restrict__ out) {
    int tok = blockIdx.x;
    int d   = threadIdx.x;
    int gw = tok & 31, gh = (tok >> 5) & 31;
    float c = 4.0f * t[tok * Dd + d];
    if (gh > 0)  c -= t[(tok - 32) * Dd + d];
    if (gh < 31) c -= t[(tok + 32) * Dd + d];
    if (gw > 0)  c -= t[(tok - 1) * Dd + d];
    if (gw < 31) c -= t[(tok + 1) * Dd + d];
    out[tok * Dd + d] = rndtf(c);
}

// LayerNorm (layer-0 entry only): one warp per token, 8 tokens/block
__global__ void ln_k(const float* __restrict__ h, float* __restrict__ xn,
                     const float* __restrict__ g, const float* __restrict__ b) {
    __shared__ float sg[256], sb[256];
    int tid = threadIdx.x;
    sg[tid] = g[tid];
    sb[tid] = b[tid];
    __syncthreads();
    int warp = tid >> 5, lane = tid & 31;
    int tok = blockIdx.x * 8 + warp;
    const float* hp = h + (size_t)tok * Dd + lane * 8;
    float4 v0 = *(const float4*)hp;
    float4 v1 = *(const float4*)(hp + 4);
    float s  = v0.x + v0.y + v0.z + v0.w + v1.x + v1.y + v1.z + v1.w;
    float sq = v0.x*v0.x + v0.y*v0.y + v0.z*v0.z + v0.w*v0.w
             + v1.x*v1.x + v1.y*v1.y + v1.z*v1.z + v1.w*v1.w;
    #pragma unroll
    for (int o = 16; o > 0; o >>= 1) {
        s  += __shfl_xor_sync(0xFFFFFFFFu, s,  o);
        sq += __shfl_xor_sync(0xFFFFFFFFu, sq, o);
    }
    float mean = s * (1.0f / 256.0f);
    float var  = sq * (1.0f / 256.0f) - mean * mean;
    float rstd = rsqrtf(var + 1e-5f);
    int c0 = lane * 8;
    float4 o0, o1;
    o0.x = (v0.x - mean) * rstd * sg[c0 + 0] + sb[c0 + 0];
    o0.y = (v0.y - mean) * rstd * sg[c0 + 1] + sb[c0 + 1];
    o0.z = (v0.z - mean) * rstd * sg[c0 + 2] + sb[c0 + 2];
    o0.w = (v0.w - mean) * rstd * sg[c0 + 3] + sb[c0 + 3];
    o1.x = (v1.x - mean) * rstd * sg[c0 + 4] + sb[c0 + 4];
    o1.y = (v1.y - mean) * rstd * sg[c0 + 5] + sb[c0 + 5];
    o1.z = (v1.z - mean) * rstd * sg[c0 + 6] + sb[c0 + 6];
    o1.w = (v1.w - mean) * rstd * sg[c0 + 7] + sb[c0 + 7];
    float* xp = xn + (size_t)tok * Dd + c0;
    *(float4*)xp       = o0;
    *(float4*)(xp + 4) = o1;
}

// ---------------------------------------------------------------------------
// tf32 GEMM (128x128x32, cp.async double-buffer, ldmatrix fragments).
//   MODE 0: C = val;  1: C = val + pos;  2: C += tanh(val)
//   CVTA:   round A fragments at use (A not pre-rounded)
//   SRC:    0 = A row-major [M,K];  1 = A gathered from image x (im2col)
// ---------------------------------------------------------------------------
#define TS_STRIDE 36
#define T_STAGE (128 * TS_STRIDE)

template<int MODE, int CVTA, int SRC>
__global__ void __launch_bounds__(256, 2)
gemm_tc(const float* __restrict__ A, const float* __restrict__ BT,
        const float* __restrict__ bias, float* __restrict__ C,
        const float* __restrict__ extra, int M, int N, int K)
{
    extern __shared__ float sm[];
    float* As = sm;
    float* Bs = sm + 2 * T_STAGE;

    const int tid  = threadIdx.x;
    const int warp = tid >> 5, lane = tid & 31;
    const int wm = warp >> 2, wn = warp & 3;
    const int row0 = blockIdx.y * 128, col0 = blockIdx.x * 128;
    const int g = lane >> 2, tg = lane & 3;
    const int lr = lane & 7, sel = lane >> 3;

    float acc[4][4][4];
    #pragma unroll
    for (int i = 0; i < 4; i++)
        #pragma unroll
        for (int j = 0; j < 4; j++)
            #pragma unroll
            for (int e = 0; e < 4; e++) acc[i][j][e] = 0.0f;

    auto load_tile = [&](int stage, int k0) {
        float* as = As + stage * T_STAGE;
        float* bs = Bs + stage * T_STAGE;
        #pragma unroll
        for (int i = 0; i < 4; i++) {
            int idx = tid + i * 256;
            int r = idx >> 3, c = (idx & 7) * 4;
            if (SRC == 1) {
                int tok = row0 + r, kc = k0 + c;
                int gw = tok & 31, gh = (tok >> 5) & 31, b = tok >> 10;
                int pr = kc >> 4, pc = kc & 15;
                cp16(as + r * TS_STRIDE + c,
                     A + ((size_t)(b * 512) + gh * 16 + pr) * 512 + gw * 16 + pc);
            } else {
                cp16(as + r * TS_STRIDE + c, A + (size_t)(row0 + r) * K + k0 + c);
            }
        }
        #pragma unroll
        for (int i = 0; i < 4; i++) {
            int idx = tid + i * 256;
            int r = idx >> 3, c = (idx & 7) * 4;
            cp16z(bs + r * TS_STRIDE + c, BT + (size_t)(col0 + r) * K + k0 + c,
                  (col0 + r) < N);
        }
    };

    uint32_t a_off[4], b_off[2];
    #pragma unroll
    for (int mi = 0; mi < 4; mi++) {
        int r = wm * 64 + mi * 16 + lr + (sel & 1) * 8;
        a_off[mi] = (uint32_t)((r * TS_STRIDE + (sel >> 1) * 4) * 4);
    }
    #pragma unroll
    for (int njp = 0; njp < 2; njp++) {
        int r = wn * 32 + njp * 16 + lr + (sel >> 1) * 8;
        b_off[njp] = (uint32_t)((r * TS_STRIDE + (sel & 1) * 4) * 4);
    }

    const uint32_t as_base = (uint32_t)__cvta_generic_to_shared(As);
    const uint32_t bs_base = (uint32_t)__cvta_generic_to_shared(Bs);

    const int ntiles = K >> 5;
    load_tile(0, 0);
    CP_COMMIT();

    for (int t = 0; t < ntiles; t++) {
        int cur = t & 1;
        if (t + 1 < ntiles) {
            load_tile(cur ^ 1, (t + 1) << 5);
            CP_COMMIT();
            CP_WAIT1();
        } else {
            CP_WAIT0();
        }
        __syncthreads();

        uint32_t as_st = as_base + cur * (T_STAGE * 4);
        uint32_t bs_st = bs_base + cur * (T_STAGE * 4);
        #pragma unroll
        for (int kk = 0; kk < 4; kk++) {
            const uint32_t kboff = (uint32_t)(kk * 8 * 4);
            uint32_t af[4][4], bf[4][2];
            #pragma unroll
            for (int mi = 0; mi < 4; mi++) {
                ldsm4(af[mi][0], af[mi][1], af[mi][2], af[mi][3],
                      as_st + a_off[mi] + kboff);
                if (CVTA) {
                    #pragma unroll
                    for (int e = 0; e < 4; e++)
                        af[mi][e] = f2tf(__uint_as_float(af[mi][e]));
                }
            }
            #pragma unroll
            for (int njp = 0; njp < 2; njp++)
                ldsm4(bf[2*njp][0], bf[2*njp][1], bf[2*njp+1][0], bf[2*njp+1][1],
                      bs_st + b_off[njp] + kboff);

            #pragma unroll
            for (int mi = 0; mi < 4; mi++)
                #pragma unroll
                for (int nj = 0; nj < 4; nj++)
                    MMA_TF32(acc[mi][nj], af[mi], bf[nj][0], bf[nj][1]);
        }
        __syncthreads();
    }

    #pragma unroll
    for (int mi = 0; mi < 4; mi++) {
        #pragma unroll
        for (int nj = 0; nj < 4; nj++) {
            int r0 = row0 + wm * 64 + mi * 16 + g;
            int c0 = col0 + wn * 32 + nj * 8 + tg * 2;
            #pragma unroll
            for (int e = 0; e < 4; e++) {
                int r = r0 + (e >> 1) * 8;
                int c = c0 + (e & 1);
                if (c < N) {
                    float val = acc[mi][nj][e] + bias[c];
                    size_t idx = (size_t)r * N + c;
                    if (MODE == 0)      C[idx] = val;
                    else if (MODE == 1) C[idx] = val + extra[(size_t)(r & 1023) * N + c];
                    else                C[idx] += tanhf(val);
                }
            }
        }
    }
}

// ---------------------------------------------------------------------------
// Fused FFN: per 64-row block — LN(h) -> P=gelu(xn@W1+b1) chunked -> acc@W2
// -> h += acc + b2 -> (optional) xn = LN_next(h)
// smem floats: Ah[64*260] | P[64*68] | W1c[64*260] | W2c[256*68] | ln params
// ---------------------------------------------------------------------------
#define FA_OFF   0
#define FP_OFF   16640
#define FW1_OFF  20992
#define FW2_OFF  37632
#define FLG_OFF  55040
#define FLB_OFF  55296
#define FLG2_OFF 55552
#define FLB2_OFF 55808
#define FFN_SMEM_FLOATS 56064
#define FFN_SMEM_BYTES  (FFN_SMEM_FLOATS * 4)

__global__ void __launch_bounds__(512, 1)
ffn_fused(float* __restrict__ h, float* __restrict__ xn,
          const float* __restrict__ w1p, const float* __restrict__ b1p,
          const float* __restrict__ w2p, const float* __restrict__ b2p,
          const float* __restrict__ lg, const float* __restrict__ lb,
          const float* __restrict__ lg2, const float* __restrict__ lb2,
          int write_xn)
{
    extern __shared__ float sm[];
    const int tid = threadIdx.x;
    const int w = tid >> 5, lane = tid & 31;
    const int row0 = blockIdx.x * 64;
    const int lr = lane & 7, sel = lane >> 3;
    const int g = lane >> 2, tg = lane & 3;
    const int wr = w >> 2, wc = w & 3;

    if (tid < 256) {
        sm[FLG_OFF + tid]  = lg[tid];
        sm[FLB_OFF + tid]  = lb[tid];
        sm[FLG2_OFF + tid] = lg2[tid];
        sm[FLB2_OFF + tid] = lb2[tid];
    }
    __syncthreads();

    // --- LN prologue: Ah = rnd(LN(h)) ---
    #pragma unroll
    for (int it = 0; it < 4; it++) {
        int r = it * 16 + w;
        const float* hp = h + (size_t)(row0 + r) * Dd + lane * 8;
        float4 v0 = *(const float4*)hp;
        float4 v1 = *(const float4*)(hp + 4);
        float s  = v0.x + v0.y + v0.z + v0.w + v1.x + v1.y + v1.z + v1.w;
        float sq = v0.x*v0.x + v0.y*v0.y + v0.z*v0.z + v0.w*v0.w
                 + v1.x*v1.x + v1.y*v1.y + v1.z*v1.z + v1.w*v1.w;
        #pragma unroll
        for (int o = 16; o > 0; o >>= 1) {
            s  += __shfl_xor_sync(0xFFFFFFFFu, s,  o);
            sq += __shfl_xor_sync(0xFFFFFFFFu, sq, o);
        }
        float mean = s * (1.0f / 256.0f);
        float rstd = rsqrtf(sq * (1.0f / 256.0f) - mean * mean + 1e-5f);
        int c0 = lane * 8;
        float* ap = sm + FA_OFF + r * 260 + c0;
        float vals[8] = {v0.x, v0.y, v0.z, v0.w, v1.x, v1.y, v1.z, v1.w};
        #pragma unroll
        for (int e = 0; e < 8; e++)
            ap[e] = rndtf((vals[e] - mean) * rstd * sm[FLG_OFF + c0 + e] + sm[FLB_OFF + c0 + e]);
    }
    __syncthreads();

    float acc2[4][2][4];
    #pragma unroll
    for (int j = 0; j < 4; j++)
        #pragma unroll
        for (int t = 0; t < 2; t++)
            #pragma unroll
            for (int e = 0; e < 4; e++) acc2[j][t][e] = 0.0f;

    const uint32_t smb = (uint32_t)__cvta_generic_to_shared(sm);
    const uint32_t a1_off = (uint32_t)((FA_OFF + (wr*16 + lr + (sel&1)*8) * 260 + (sel>>1)*4) * 4);
    const uint32_t b1_off = (uint32_t)((FW1_OFF + (wc*16 + lr + (sel>>1)*8) * 260 + (sel&1)*4) * 4);
    const uint32_t a2_off = (uint32_t)((FP_OFF + (wr*16 + lr + (sel&1)*8) * 68 + (sel>>1)*4) * 4);
    uint32_t b2_off[4];
    #pragma unroll
    for (int j = 0; j < 4; j++)
        b2_off[j] = (uint32_t)((FW2_OFF + (wc*64 + j*16 + lr + (sel>>1)*8) * 68 + (sel&1)*4) * 4);

    for (int c = 0; c < 16; c++) {
        // load W1 chunk [64n x 256k] and W2 chunk [256n x 64k]
        for (int i = tid; i < 4096; i += 512) {
            int r = i >> 6, cc = (i & 63) * 4;
            cp16(sm + FW1_OFF + r * 260 + cc, w1p + (size_t)(c * 64 + r) * 256 + cc);
        }
        for (int i = tid; i < 4096; i += 512) {
            int r = i >> 4, cc = (i & 15) * 4;
            cp16(sm + FW2_OFF + r * 68 + cc, w2p + (size_t)r * 1024 + c * 64 + cc);
        }
        CP_COMMIT();
        CP_WAIT0();
        __syncthreads();

        // GEMM1: out m16(wr) x n16(wc), K=256
        float acc1[2][4];
        #pragma unroll
        for (int t = 0; t < 2; t++)
            #pragma unroll
            for (int e = 0; e < 4; e++) acc1[t][e] = 0.0f;
        #pragma unroll
        for (int kk = 0; kk < 32; kk++) {
            const uint32_t ko = (uint32_t)(kk * 8 * 4);
            uint32_t af[4], bf[4];
            ldsm4(af[0], af[1], af[2], af[3], smb + a1_off + ko);
            ldsm4(bf[0], bf[1], bf[2], bf[3], smb + b1_off + ko);
            MMA_TF32(acc1[0], af, bf[0], bf[1]);
            MMA_TF32(acc1[1], af, bf[2], bf[3]);
        }

        // gelu -> P
        #pragma unroll
        for (int t = 0; t < 2; t++)
            #pragma unroll
            for (int e = 0; e < 4; e++) {
                int rr = wr * 16 + g + (e >> 1) * 8;
                int cc = wc * 16 + t * 8 + tg * 2 + (e & 1);
                float val = acc1[t][e] + b1p[c * 64 + cc];
                val = val * 0.5f * (1.0f + erff(val * 0.70710678118654752f));
                sm[FP_OFF + rr * 68 + cc] = rndtf(val);
            }
        __syncthreads();

        // GEMM2: acc2 += P @ W2c ; out m16(wr) x n64(wc), K=64
        #pragma unroll
        for (int kk = 0; kk < 8; kk++) {
            const uint32_t ko = (uint32_t)(kk * 8 * 4);
            uint32_t af[4];
            ldsm4(af[0], af[1], af[2], af[3], smb + a2_off + ko);
            #pragma unroll
            for (int j = 0; j < 4; j++) {
                uint32_t bf[4];
                ldsm4(bf[0], bf[1], bf[2], bf[3], smb + b2_off[j] + ko);
                MMA_TF32(acc2[j][0], af, bf[0], bf[1]);
                MMA_TF32(acc2[j][1], af, bf[2], bf[3]);
            }
        }
        __syncthreads();
    }

    // --- epilogue: Hs (reuse W1c region) = h + acc2 + b2 ---
    for (int i = tid; i < 4096; i += 512) {
        int r = i >> 6, cc = (i & 63) * 4;
        *(float4*)(sm + FW1_OFF + r * 260 + cc) =
            *(const float4*)(h + (size_t)(row0 + r) * Dd + cc);
    }
    __syncthreads();
    #pragma unroll
    for (int j = 0; j < 4; j++)
        #pragma unroll
        for (int t = 0; t < 2; t++)
            #pragma unroll
            for (int e = 0; e < 4; e++) {
                int rr = wr * 16 + g + (e >> 1) * 8;
                int cc = wc * 64 + j * 16 + t * 8 + tg * 2 + (e & 1);
                sm[FW1_OFF + rr * 260 + cc] += acc2[j][t][e] + b2p[cc];
            }
    __syncthreads();

    // write h (+ optional next-layer LN -> xn)
    #pragma unroll
    for (int it = 0; it < 4; it++) {
        int r = it * 16 + w;
        const float* hs = sm + FW1_OFF + r * 260 + lane * 8;
        float4 v0 = *(const float4*)hs;
        float4 v1 = *(const float4*)(hs + 4);
        float* hp = h + (size_t)(row0 + r) * Dd + lane * 8;
        *(float4*)hp       = v0;
        *(float4*)(hp + 4) = v1;
        if (write_xn) {
            float s  = v0.x + v0.y + v0.z + v0.w + v1.x + v1.y + v1.z + v1.w;
            float sq = v0.x*v0.x + v0.y*v0.y + v0.z*v0.z + v0.w*v0.w
                     + v1.x*v1.x + v1.y*v1.y + v1.z*v1.z + v1.w*v1.w;
            #pragma unroll
            for (int o = 16; o > 0; o >>= 1) {
                s  += __shfl_xor_sync(0xFFFFFFFFu, s,  o);
                sq += __shfl_xor_sync(0xFFFFFFFFu, sq, o);
            }
            float mean = s * (1.0f / 256.0f);
            float rstd = rsqrtf(sq * (1.0f / 256.0f) - mean * mean + 1e-5f);
            int c0 = lane * 8;
            float vals[8] = {v0.x, v0.y, v0.z, v0.w, v1.x, v1.y, v1.z, v1.w};
            float* xp = xn + (size_t)(row0 + r) * Dd + c0;
            #pragma unroll
            for (int e = 0; e < 8; e++)
                xp[e] = (vals[e] - mean) * rstd * sm[FLG2_OFF + c0 + e] + sm[FLB2_OFF + c0 + e];
        }
    }
}

// ---------------------------------------------------------------------------
// Attention scores + softmax: one warp per token -> att[tok][64]
// ---------------------------------------------------------------------------
__global__ void attn_score_k(const float* __restrict__ qkv, float* __restrict__ att)
{
    int warp = threadIdx.x >> 5;
    int lane = threadIdx.x & 31;
    int tok = blockIdx.x * 8 + warp;
    int gw = tok & 31, gh = (tok >> 5) & 31, b = tok >> 10;

    __shared__ float qs[8][32];
    qs[warp][lane] = qkv[(size_t)tok * QKVW + lane];
    __syncwarp();

    const float* krow = qkv + (size_t)(b * Nn + gh * 32 + lane) * QKVW + 32;
    const float* kcol = qkv + (size_t)(b * Nn + lane * 32 + gw) * QKVW + 32;
    float sr = 0.f, sc = 0.f;
    #pragma unroll
    for (int c = 0; c < 32; c += 4) {
        float4 kr = *(const float4*)(krow + c);
        float4 kc = *(const float4*)(kcol + c);
        float q0 = qs[warp][c], q1 = qs[warp][c + 1], q2 = qs[warp][c + 2], q3 = qs[warp][c + 3];
        sr = fmaf(q0, kr.x, fmaf(q1, kr.y, fmaf(q2, kr.z, fmaf(q3, kr.w, sr))));
        sc = fmaf(q0, kc.x, fmaf(q1, kc.y, fmaf(q2, kc.z, fmaf(q3, kc.w, sc))));
    }
    const float scale = 0.17677669529663687f;   // 1/sqrt(32)
    sr *= scale;
    sc *= scale;
    if (lane == gh) sc -= 1e9f;

    float m2 = fmaxf(sr, sc);
    #pragma unroll
    for (int o = 16; o > 0; o >>= 1) m2 = fmaxf(m2, __shfl_xor_sync(0xFFFFFFFFu, m2, o));
    float e0 = expf(sr - m2), e1 = expf(sc - m2);
    float s = e0 + e1;
    #pragma unroll
    for (int o = 16; o > 0; o >>= 1) s += __shfl_xor_sync(0xFFFFFFFFu, s, o);
    float inv = 1.0f / s;
    att[(size_t)tok * 64 + lane]      = e0 * inv;
    att[(size_t)tok * 64 + 32 + lane] = e1 * inv;
}

// ---------------------------------------------------------------------------
// Apply row attention: block = (b, gh); h += xn + gamma * out_row
// ---------------------------------------------------------------------------
__global__ void attn_apply_row_k(const float* __restrict__ att, const float* __restrict__ qkv,
                                 const float* __restrict__ xn, float* __restrict__ h,
                                 const float* __restrict__ gamma_all, int layer)
{
    int blk = blockIdx.x;
    int b = blk >> 5, gh = blk & 31;
    int d = threadIdx.x;
    int base_tok = b * Nn + gh * 32;

    __shared__ float as_[32][32];
    for (int i = d; i < 1024; i += 256) {
        int t = i >> 5, j = i & 31;
        as_[t][j] = att[(size_t)(base_tok + t) * 64 + j];
    }
    __syncthreads();

    float acc[32];
    #pragma unroll
    for (int t = 0; t < 32; t++) acc[t] = 0.f;

    const float* vp = qkv + (size_t)base_tok * QKVW + 64 + d;
    #pragma unroll 4
    for (int j = 0; j < 32; j++) {
        float vj = vp[j * QKVW];
        #pragma unroll
        for (int t = 0; t < 32; t++) acc[t] = fmaf(as_[t][j], vj, acc[t]);
    }
    float gm = gamma_all[layer];
    #pragma unroll
    for (int t = 0; t < 32; t++) {
        size_t idx = (size_t)(base_tok + t) * Dd + d;
        h[idx] += xn[idx] + gm * acc[t];
    }
}

// ---------------------------------------------------------------------------
// Apply column attention: block = (b, gw); h += gamma * out_col
// ---------------------------------------------------------------------------
__global__ void attn_apply_col_k(const float* __restrict__ att, const float* __restrict__ qkv,
                                 float* __restrict__ h,
                                 const float* __restrict__ gamma_all, int layer)
{
    int blk = blockIdx.x;
    int b = blk >> 5, gw = blk & 31;
    int d = threadIdx.x;

    __shared__ float as_[32][32];
    for (int i = d; i < 1024; i += 256) {
        int t = i >> 5, j = i & 31;
        as_[t][j] = att[(size_t)(b * Nn + t * 32 + gw) * 64 + 32 + j];
    }
    __syncthreads();

    float acc[32];
    #pragma unroll
    for (int t = 0; t < 32; t++) acc[t] = 0.f;

    #pragma unroll 4
    for (int j = 0; j < 32; j++) {
        float vj = qkv[(size_t)(b * Nn + j * 32 + gw) * QKVW + 64 + d];
        #pragma unroll
        for (int t = 0; t < 32; t++) acc[t] = fmaf(as_[t][j], vj, acc[t]);
    }
    float gm = gamma_all[layer];
    #pragma unroll
    for (int t = 0; t < 32; t++) {
        size_t idx = (size_t)(b * Nn + t * 32 + gw) * Dd + d;
        h[idx] += gm * acc[t];
    }
}

// ---------------------------------------------------------------------------
__global__ void head_k(const float* __restrict__ h, const float* __restrict__ w,
                       const float* __restrict__ bh, float* __restrict__ out)
{
    int m = blockIdx.x;
    int d = threadIdx.x;
    float p = h[(size_t)m * Dd + d] * w[d];
    #pragma unroll
    for (int o = 16; o > 0; o >>= 1) p += __shfl_xor_sync(0xFFFFFFFFu, p, o);
    __shared__ float s1[8];
    int lane = d & 31, wr = d >> 5;
    if (lane == 0) s1[wr] = p;
    __syncthreads();
    if (d == 0) {
        float S = 0;
        #pragma unroll
        for (int i = 0; i < 8; i++) S += s1[i];
        out[m] = S + bh[0];
    }
}

// ---------------------------------------------------------------------------
extern "C" void kernel_launch(void* const* d_in, const int* in_sizes, int n_in,
                              void* d_out, int out_size)
{
    const float* x       = (const float*)d_in[0];
    const float* w_patch = (const float*)d_in[1];
    const float* b_patch = (const float*)d_in[2];
    const float* pos     = (const float*)d_in[3];
    const float* w_edge  = (const float*)d_in[4];
    const float* b_edge  = (const float*)d_in[5];
    const float* ln_g    = (const float*)d_in[6];
    const float* ln_b    = (const float*)d_in[7];
    const float* wq      = (const float*)d_in[8];
    const float* bq      = (const float*)d_in[9];
    const float* wk      = (const float*)d_in[10];
    const float* bk      = (const float*)d_in[11];
    const float* wv      = (const float*)d_in[12];
    const float* bv      = (const float*)d_in[13];
    const float* gamma   = (const float*)d_in[14];
    const float* w1      = (const float*)d_in[15];
    const float* b1      = (const float*)d_in[16];
    const float* w2      = (const float*)d_in[17];
    const float* b2      = (const float*)d_in[18];
    const float* w_head  = (const float*)d_in[19];
    const float* b_head  = (const float*)d_in[20];
    float* out = (float*)d_out;

    float *h, *xn, *lap, *qkv, *att;
    float *wpT, *weT, *wqkvT, *bqkv, *w1T, *w2T;
    cudaGetSymbolAddress((void**)&h,     g_h);
    cudaGetSymbolAddress((void**)&xn,    g_xn);
    cudaGetSymbolAddress((void**)&lap,   g_lap);
    cudaGetSymbolAddress((void**)&qkv,   g_qkv);
    cudaGetSymbolAddress((void**)&att,   g_att);
    cudaGetSymbolAddress((void**)&wpT,   g_wpT);
    cudaGetSymbolAddress((void**)&weT,   g_weT);
    cudaGetSymbolAddress((void**)&wqkvT, g_wqkvT);
    cudaGetSymbolAddress((void**)&bqkv,  g_bqkv);
    cudaGetSymbolAddress((void**)&w1T,   g_w1T);
    cudaGetSymbolAddress((void**)&w2T,   g_w2T);

    const int SMEM = 4 * T_STAGE * 4;   // 73728 bytes
    static bool attr_done = false;
    if (!attr_done) {
        cudaFuncSetAttribute(gemm_tc<1,1,1>, cudaFuncAttributeMaxDynamicSharedMemorySize, SMEM);
        cudaFuncSetAttribute(gemm_tc<2,0,0>, cudaFuncAttributeMaxDynamicSharedMemorySize, SMEM);
        cudaFuncSetAttribute(gemm_tc<0,1,0>, cudaFuncAttributeMaxDynamicSharedMemorySize, SMEM);
        cudaFuncSetAttribute(ffn_fused, cudaFuncAttributeMaxDynamicSharedMemorySize, FFN_SMEM_BYTES);
        attr_done = true;
    }

    const int M = Mtok;
    dim3 b256(256);

    // [0] all small weight prep
    prep_all_k<<<2880, b256>>>(w_patch, w_edge, wq, wk, wv, bq, bk, bv,
                               wpT, weT, wqkvT, bqkv);
    // [1] patch embed (im2col fused into A load)
    gemm_tc<1,1,1><<<dim3(2, M / 128), b256, SMEM>>>(x, wpT, b_patch, h, pos, M, Dd, Dd);
    // [2] laplacian, [3] edge GEMM: h += tanh(lap @ w_edge + b_edge)
    lap_k<<<Mtok, b256>>>(h, lap);
    gemm_tc<2,0,0><<<dim3(2, M / 128), b256, SMEM>>>(lap, weT, b_edge, h, nullptr, M, Dd, Dd);
    // [4] layer-0 ln1
    ln_k<<<Mtok / 8, b256>>>(h, xn, ln_g, ln_b);

    bool big_done = false;
    for (int l = 0; l < 8; l++) {
        // [5 on l==0] qkv GEMM — ncu capture target
        gemm_tc<0,1,0><<<dim3(3, M / 128), b256, SMEM>>>(xn, wqkvT + (size_t)l * QKVW * Dd,
                                                         bqkv + l * QKVW, qkv, nullptr, M, QKVW, Dd);
        if (!big_done) {
            transpose_big_k<<<dim3(32, 32, 16), b256>>>(w1, w2, w1T, w2T);
            big_done = true;
        }
        attn_score_k<<<Mtok / 8, b256>>>(qkv, att);
        attn_apply_row_k<<<Mtok / 32, b256>>>(att, qkv, xn, h, gamma, l);
        attn_apply_col_k<<<Mtok / 32, b256>>>(att, qkv, h, gamma, l);

        int nl = (l < 7) ? l + 1 : l;
        ffn_fused<<<M / 64, 512, FFN_SMEM_BYTES>>>(
            h, xn,
            w1T + (size_t)l * DFf * Dd, b1 + l * DFf,
            w2T + (size_t)l * Dd * DFf, b2 + l * Dd,
            ln_g + l * Dd, ln_b + l * Dd,
            ln_g + nl * Dd, ln_b + nl * Dd,
            (l < 7) ? 1 : 0);
    }

    head_k<<<Mtok, b256>>>(h, w_head, b_head, out);
}

// round 9
// speedup vs baseline: 1.1859x; 1.1859x over previous
#include <cuda_runtime.h>
#include <cuda_bf16.h>
#include <math.h>
#include <stdint.h>

// ---------------------------------------------------------------------------
// BoundaryAwareViT — mma.sync tf32 GEMMs, 3-stage cp.async pipeline.
// B=32, IMG=512, P=16, D=256, DEPTH=8, G=32, N=1024, DQ=32, DF=1024, M=32768
// (tcgen05 rejected by harness PTX target compute_103 — mma.sync only.)
// ---------------------------------------------------------------------------

#define Mtok  32768
#define Dd    256
#define DFf   1024
#define Nn    1024
#define QKVW  320        // 32 q + 32 k + 256 v

__device__ float g_h   [Mtok * Dd];
__device__ float g_xn  [Mtok * Dd];
__device__ float g_lap [Mtok * Dd];
__device__ float g_qkv [Mtok * QKVW];
__device__ float g_mid [Mtok * DFf];
__device__ float g_att [Mtok * 64];
__device__ float g_wpT [Dd * Dd];          // patch weight [n][k], rounded
__device__ float g_weT [Dd * Dd];          // edge weight transposed [n][k]
__device__ float g_wqkvT[8 * QKVW * Dd];   // [l][c][k] rounded
__device__ float g_bqkv [8 * QKVW];
__device__ float g_w1T [8 * DFf * Dd];     // [l][1024][256] rounded
__device__ float g_w2T [8 * Dd * DFf];     // [l][256][1024] rounded

__device__ __forceinline__ uint32_t f2tf(float f) {
    uint32_t u;
    asm("cvt.rna.tf32.f32 %0, %1;" : "=r"(u) : "f"(f));
    return u;
}
__device__ __forceinline__ float rndtf(float f) { return __uint_as_float(f2tf(f)); }

// ---------------------------------------------------------------------------
// cp.async / ldmatrix helpers
// ---------------------------------------------------------------------------
__device__ __forceinline__ void cp16(float* s, const float* g) {
    uint32_t sa = (uint32_t)__cvta_generic_to_shared(s);
    asm volatile("cp.async.cg.shared.global [%0], [%1], 16;" :: "r"(sa), "l"(g));
}
__device__ __forceinline__ void cp16z(float* s, const float* g, bool valid) {
    uint32_t sa = (uint32_t)__cvta_generic_to_shared(s);
    int sz = valid ? 16 : 0;
    asm volatile("cp.async.cg.shared.global [%0], [%1], 16, %2;" :: "r"(sa), "l"(g), "r"(sz));
}
#define CP_COMMIT() asm volatile("cp.async.commit_group;" ::: "memory")
#define CP_WAIT1()  asm volatile("cp.async.wait_group 1;" ::: "memory")
#define CP_WAIT0()  asm volatile("cp.async.wait_group 0;" ::: "memory")

__device__ __forceinline__ void ldsm4(uint32_t& r0, uint32_t& r1, uint32_t& r2, uint32_t& r3,
                                      uint32_t addr) {
    asm volatile("ldmatrix.sync.aligned.m8n8.x4.shared.b16 {%0,%1,%2,%3}, [%4];"
                 : "=r"(r0), "=r"(r1), "=r"(r2), "=r"(r3) : "r"(addr));
}
#define MMA_TF32(acc, a, b0, b1)                                               \
    asm volatile("mma.sync.aligned.m16n8k8.row.col.f32.tf32.tf32.f32 "         \
                 "{%0,%1,%2,%3}, {%4,%5,%6,%7}, {%8,%9}, {%0,%1,%2,%3};"       \
                 : "+f"(acc[0]), "+f"(acc[1]), "+f"(acc[2]), "+f"(acc[3])      \
                 : "r"(a[0]), "r"(a[1]), "r"(a[2]), "r"(a[3]), "r"(b0), "r"(b1))

// ---------------------------------------------------------------------------
// prep kernels
// ---------------------------------------------------------------------------
__global__ void prep_all_k(const float* __restrict__ wp, const float* __restrict__ we,
                           const float* __restrict__ wq, const float* __restrict__ wk,
                           const float* __restrict__ wv, const float* __restrict__ bq,
                           const float* __restrict__ bk, const float* __restrict__ bv,
                           float* __restrict__ wpT, float* __restrict__ weT,
                           float* __restrict__ wqkvT, float* __restrict__ bqkv)
{
    int bx = blockIdx.x, tid = threadIdx.x;
    if (bx < 256) {
        int i = bx * 256 + tid;
        wpT[i] = rndtf(wp[i]);
    } else if (bx < 320) {
        __shared__ float t[32][33];
        int tile = bx - 256;
        int r0 = (tile >> 3) * 32, c0 = (tile & 7) * 32;
        int tx = tid & 31, ty = tid >> 5;
        #pragma unroll
        for (int i = 0; i < 32; i += 8)
            t[ty + i][tx] = we[(r0 + ty + i) * 256 + c0 + tx];
        __syncthreads();
        #pragma unroll
        for (int i = 0; i < 32; i += 8)
            weT[(c0 + ty + i) * 256 + r0 + tx] = rndtf(t[tx][ty + i]);
    } else {
        int idx = (bx - 320) * 256 + tid;   // 8*320*256
        int k  = idx & 255;
        int c  = (idx >> 8) % QKVW;
        int l  = idx / (QKVW * 256);
        float val;
        if (c < 32)      val = wq[(l * 256 + k) * 32 + c];
        else if (c < 64) val = wk[(l * 256 + k) * 32 + (c - 32)];
        else             val = wv[(l * 256 + k) * 256 + (c - 64)];
        wqkvT[idx] = rndtf(val);
        if (idx < 8 * QKVW) {
            int l2 = idx / QKVW, c2 = idx % QKVW;
            bqkv[idx] = (c2 < 32) ? bq[l2 * 32 + c2]
                      : (c2 < 64) ? bk[l2 * 32 + c2 - 32]
                                  : bv[l2 * 256 + c2 - 64];
        }
    }
}

__global__ void transpose_big_k(const float* __restrict__ w1, const float* __restrict__ w2,
                                float* __restrict__ w1T, float* __restrict__ w2T)
{
    __shared__ float t[32][33];
    int z = blockIdx.z;
    const float* src; float* dst; int C;
    if (z < 8) { src = w1 + (size_t)z * 256 * 1024;      dst = w1T + (size_t)z * 256 * 1024;      C = 1024; if (blockIdx.y >= 8) return; }
    else       { src = w2 + (size_t)(z - 8) * 256 * 1024; dst = w2T + (size_t)(z - 8) * 256 * 1024; C = 256;  if (blockIdx.x >= 8) return; }
    int R = (z < 8) ? 256 : 1024;
    int c0 = blockIdx.x * 32, r0 = blockIdx.y * 32;
    int tx = threadIdx.x & 31, ty = threadIdx.x >> 5;
    #pragma unroll
    for (int i = 0; i < 32; i += 8)
        t[ty + i][tx] = src[(size_t)(r0 + ty + i) * C + c0 + tx];
    __syncthreads();
    #pragma unroll
    for (int i = 0; i < 32; i += 8)
        dst[(size_t)(c0 + ty + i) * R + r0 + tx] = rndtf(t[tx][ty + i]);
}

__global__ void lap_k(const float* __restrict__ t, float* __restrict__ out) {
    int tok = blockIdx.x;
    int d   = threadIdx.x;
    int gw = tok & 31, gh = (tok >> 5) & 31;
    float c = 4.0f * t[tok * Dd + d];
    if (gh > 0)  c -= t[(tok - 32) * Dd + d];
    if (gh < 31) c -= t[(tok + 32) * Dd + d];
    if (gw > 0)  c -= t[(tok - 1) * Dd + d];
    if (gw < 31) c -= t[(tok + 1) * Dd + d];
    out[tok * Dd + d] = rndtf(c);
}

// LayerNorm: one warp per token, float4, warp-shuffle reduce. 8 tokens/block.
__global__ void ln_k(const float* __restrict__ h, float* __restrict__ xn,
                     const float* __restrict__ g, const float* __restrict__ b) {
    __shared__ float sg[256], sb[256];
    int tid = threadIdx.x;
    sg[tid] = g[tid];
    sb[tid] = b[tid];
    __syncthreads();
    int warp = tid >> 5, lane = tid & 31;
    int tok = blockIdx.x * 8 + warp;
    const float* hp = h + (size_t)tok * Dd + lane * 8;
    float4 v0 = *(const float4*)hp;
    float4 v1 = *(const float4*)(hp + 4);
    float s  = v0.x + v0.y + v0.z + v0.w + v1.x + v1.y + v1.z + v1.w;
    float sq = v0.x*v0.x + v0.y*v0.y + v0.z*v0.z + v0.w*v0.w
             + v1.x*v1.x + v1.y*v1.y + v1.z*v1.z + v1.w*v1.w;
    #pragma unroll
    for (int o = 16; o > 0; o >>= 1) {
        s  += __shfl_xor_sync(0xFFFFFFFFu, s,  o);
        sq += __shfl_xor_sync(0xFFFFFFFFu, sq, o);
    }
    float mean = s * (1.0f / 256.0f);
    float var  = sq * (1.0f / 256.0f) - mean * mean;
    float rstd = rsqrtf(var + 1e-5f);
    int c0 = lane * 8;
    float4 o0, o1;
    o0.x = (v0.x - mean) * rstd * sg[c0 + 0] + sb[c0 + 0];
    o0.y = (v0.y - mean) * rstd * sg[c0 + 1] + sb[c0 + 1];
    o0.z = (v0.z - mean) * rstd * sg[c0 + 2] + sb[c0 + 2];
    o0.w = (v0.w - mean) * rstd * sg[c0 + 3] + sb[c0 + 3];
    o1.x = (v1.x - mean) * rstd * sg[c0 + 4] + sb[c0 + 4];
    o1.y = (v1.y - mean) * rstd * sg[c0 + 5] + sb[c0 + 5];
    o1.z = (v1.z - mean) * rstd * sg[c0 + 6] + sb[c0 + 6];
    o1.w = (v1.w - mean) * rstd * sg[c0 + 7] + sb[c0 + 7];
    float* xp = xn + (size_t)tok * Dd + c0;
    *(float4*)xp       = o0;
    *(float4*)(xp + 4) = o1;
}

// ---------------------------------------------------------------------------
// tf32 GEMM: C[M,N] = A[M,K] @ BT[N,K]^T + bias. 128x128x32 tiles,
// THREE-stage cp.async pipeline, ldmatrix fragment loads.
//   MODE 0: C=val; 1: C=val+pos; 2: C+=tanh(val); 3: C=rnd(gelu(val)); 4: C+=val
//   CVTA:   round A fragments at use (A not pre-rounded)
//   SRC:    0 = A row-major [M,K];  1 = A gathered from image x (im2col)
// Dyn smem: 3 * 2 * 128*36 * 4 = 110592 B  (2 CTAs/SM)
// ---------------------------------------------------------------------------
#define TS_STRIDE 36
#define T_STAGE (128 * TS_STRIDE)
#define N_STAGES 3

template<int MODE, int CVTA, int SRC>
__global__ void __launch_bounds__(256, 2)
gemm_tc(const float* __restrict__ A, const float* __restrict__ BT,
        const float* __restrict__ bias, float* __restrict__ C,
        const float* __restrict__ extra, int M, int N, int K)
{
    extern __shared__ float sm[];
    float* As = sm;                                 // [3][128][36]
    float* Bs = sm + N_STAGES * T_STAGE;            // [3][128][36]

    const int tid  = threadIdx.x;
    const int warp = tid >> 5, lane = tid & 31;
    const int wm = warp >> 2, wn = warp & 3;
    const int row0 = blockIdx.y * 128, col0 = blockIdx.x * 128;
    const int g = lane >> 2, tg = lane & 3;
    const int lr = lane & 7, sel = lane >> 3;

    float acc[4][4][4];
    #pragma unroll
    for (int i = 0; i < 4; i++)
        #pragma unroll
        for (int j = 0; j < 4; j++)
            #pragma unroll
            for (int e = 0; e < 4; e++) acc[i][j][e] = 0.0f;

    auto load_tile = [&](int stage, int k0) {
        float* as = As + stage * T_STAGE;
        float* bs = Bs + stage * T_STAGE;
        #pragma unroll
        for (int i = 0; i < 4; i++) {
            int idx = tid + i * 256;
            int r = idx >> 3, c = (idx & 7) * 4;
            if (SRC == 1) {
                int tok = row0 + r, kc = k0 + c;
                int gw = tok & 31, gh = (tok >> 5) & 31, b = tok >> 10;
                int pr = kc >> 4, pc = kc & 15;
                cp16(as + r * TS_STRIDE + c,
                     A + ((size_t)(b * 512) + gh * 16 + pr) * 512 + gw * 16 + pc);
            } else {
                cp16(as + r * TS_STRIDE + c, A + (size_t)(row0 + r) * K + k0 + c);
            }
        }
        #pragma unroll
        for (int i = 0; i < 4; i++) {
            int idx = tid + i * 256;
            int r = idx >> 3, c = (idx & 7) * 4;
            cp16z(bs + r * TS_STRIDE + c, BT + (size_t)(col0 + r) * K + k0 + c,
                  (col0 + r) < N);
        }
    };

    uint32_t a_off[4], b_off[2];
    #pragma unroll
    for (int mi = 0; mi < 4; mi++) {
        int r = wm * 64 + mi * 16 + lr + (sel & 1) * 8;
        a_off[mi] = (uint32_t)((r * TS_STRIDE + (sel >> 1) * 4) * 4);
    }
    #pragma unroll
    for (int njp = 0; njp < 2; njp++) {
        int r = wn * 32 + njp * 16 + lr + (sel >> 1) * 8;
        b_off[njp] = (uint32_t)((r * TS_STRIDE + (sel & 1) * 4) * 4);
    }

    const uint32_t as_base = (uint32_t)__cvta_generic_to_shared(As);
    const uint32_t bs_base = (uint32_t)__cvta_generic_to_shared(Bs);

    const int ntiles = K >> 5;          // K >= 256 always here
    load_tile(0, 0);
    CP_COMMIT();
    load_tile(1, 32);
    CP_COMMIT();
    CP_WAIT1();                          // stage 0 resident
    __syncthreads();

    int cur = 0, nxt = 2;                // nxt = stage receiving load t+2
    for (int t = 0; t < ntiles; t++) {
        if (t + 2 < ntiles) {
            load_tile(nxt, (t + 2) << 5);
            CP_COMMIT();
        }

        uint32_t as_st = as_base + cur * (T_STAGE * 4);
        uint32_t bs_st = bs_base + cur * (T_STAGE * 4);
        #pragma unroll
        for (int kk = 0; kk < 4; kk++) {
            const uint32_t kboff = (uint32_t)(kk * 8 * 4);
            uint32_t af[4][4], bf[4][2];
            #pragma unroll
            for (int mi = 0; mi < 4; mi++) {
                ldsm4(af[mi][0], af[mi][1], af[mi][2], af[mi][3],
                      as_st + a_off[mi] + kboff);
                if (CVTA) {
                    #pragma unroll
                    for (int e = 0; e < 4; e++)
                        af[mi][e] = f2tf(__uint_as_float(af[mi][e]));
                }
            }
            #pragma unroll
            for (int njp = 0; njp < 2; njp++)
                ldsm4(bf[2*njp][0], bf[2*njp][1], bf[2*njp+1][0], bf[2*njp+1][1],
                      bs_st + b_off[njp] + kboff);

            #pragma unroll
            for (int mi = 0; mi < 4; mi++)
                #pragma unroll
                for (int nj = 0; nj < 4; nj++)
                    MMA_TF32(acc[mi][nj], af[mi], bf[nj][0], bf[nj][1]);
        }

        if (t + 1 < ntiles) {
            if (t + 2 < ntiles) CP_WAIT1();   // next stage resident
            else                CP_WAIT0();
            __syncthreads();
        }
        cur = (cur == N_STAGES - 1) ? 0 : cur + 1;
        nxt = (nxt == N_STAGES - 1) ? 0 : nxt + 1;
    }

    #pragma unroll
    for (int mi = 0; mi < 4; mi++) {
        #pragma unroll
        for (int nj = 0; nj < 4; nj++) {
            int r0 = row0 + wm * 64 + mi * 16 + g;
            int c0 = col0 + wn * 32 + nj * 8 + tg * 2;
            #pragma unroll
            for (int e = 0; e < 4; e++) {
                int r = r0 + (e >> 1) * 8;
                int c = c0 + (e & 1);
                if (c < N) {
                    float val = acc[mi][nj][e] + bias[c];
                    size_t idx = (size_t)r * N + c;
                    if (MODE == 0) {
                        C[idx] = val;
                    } else if (MODE == 1) {
                        C[idx] = val + extra[(size_t)(r & 1023) * N + c];
                    } else if (MODE == 2) {
                        C[idx] += tanhf(val);
                    } else if (MODE == 3) {
                        C[idx] = rndtf(val * 0.5f * (1.0f + erff(val * 0.70710678118654752f)));
                    } else {
                        C[idx] += val;
                    }
                }
            }
        }
    }
}

// ---------------------------------------------------------------------------
// Attention scores + softmax: one warp per token -> att[tok][64]
// ---------------------------------------------------------------------------
__global__ void attn_score_k(const float* __restrict__ qkv, float* __restrict__ att)
{
    int warp = threadIdx.x >> 5;
    int lane = threadIdx.x & 31;
    int tok = blockIdx.x * 8 + warp;
    int gw = tok & 31, gh = (tok >> 5) & 31, b = tok >> 10;

    __shared__ float qs[8][32];
    qs[warp][lane] = qkv[(size_t)tok * QKVW + lane];
    __syncwarp();

    const float* krow = qkv + (size_t)(b * Nn + gh * 32 + lane) * QKVW + 32;
    const float* kcol = qkv + (size_t)(b * Nn + lane * 32 + gw) * QKVW + 32;
    float sr = 0.f, sc = 0.f;
    #pragma unroll
    for (int c = 0; c < 32; c += 4) {
        float4 kr = *(const float4*)(krow + c);
        float4 kc = *(const float4*)(kcol + c);
        float q0 = qs[warp][c], q1 = qs[warp][c + 1], q2 = qs[warp][c + 2], q3 = qs[warp][c + 3];
        sr = fmaf(q0, kr.x, fmaf(q1, kr.y, fmaf(q2, kr.z, fmaf(q3, kr.w, sr))));
        sc = fmaf(q0, kc.x, fmaf(q1, kc.y, fmaf(q2, kc.z, fmaf(q3, kc.w, sc))));
    }
    const float scale = 0.17677669529663687f;   // 1/sqrt(32)
    sr *= scale;
    sc *= scale;
    if (lane == gh) sc -= 1e9f;

    float m2 = fmaxf(sr, sc);
    #pragma unroll
    for (int o = 16; o > 0; o >>= 1) m2 = fmaxf(m2, __shfl_xor_sync(0xFFFFFFFFu, m2, o));
    float e0 = expf(sr - m2), e1 = expf(sc - m2);
    float s = e0 + e1;
    #pragma unroll
    for (int o = 16; o > 0; o >>= 1) s += __shfl_xor_sync(0xFFFFFFFFu, s, o);
    float inv = 1.0f / s;
    att[(size_t)tok * 64 + lane]      = e0 * inv;
    att[(size_t)tok * 64 + 32 + lane] = e1 * inv;
}

// ---------------------------------------------------------------------------
// Apply row attention: block = (b, gh); h += xn + gamma * out_row
// ---------------------------------------------------------------------------
__global__ void attn_apply_row_k(const float* __restrict__ att, const float* __restrict__ qkv,
                                 const float* __restrict__ xn, float* __restrict__ h,
                                 const float* __restrict__ gamma_all, int layer)
{
    int blk = blockIdx.x;
    int b = blk >> 5, gh = blk & 31;
    int d = threadIdx.x;
    int base_tok = b * Nn + gh * 32;

    __shared__ float as_[32][32];
    for (int i = d; i < 1024; i += 256) {
        int t = i >> 5, j = i & 31;
        as_[t][j] = att[(size_t)(base_tok + t) * 64 + j];
    }
    __syncthreads();

    float acc[32];
    #pragma unroll
    for (int t = 0; t < 32; t++) acc[t] = 0.f;

    const float* vp = qkv + (size_t)base_tok * QKVW + 64 + d;
    #pragma unroll 4
    for (int j = 0; j < 32; j++) {
        float vj = vp[j * QKVW];
        #pragma unroll
        for (int t = 0; t < 32; t++) acc[t] = fmaf(as_[t][j], vj, acc[t]);
    }
    float gm = gamma_all[layer];
    #pragma unroll
    for (int t = 0; t < 32; t++) {
        size_t idx = (size_t)(base_tok + t) * Dd + d;
        h[idx] += xn[idx] + gm * acc[t];
    }
}

// ---------------------------------------------------------------------------
// Apply column attention: block = (b, gw); h += gamma * out_col
// ---------------------------------------------------------------------------
__global__ void attn_apply_col_k(const float* __restrict__ att, const float* __restrict__ qkv,
                                 float* __restrict__ h,
                                 const float* __restrict__ gamma_all, int layer)
{
    int blk = blockIdx.x;
    int b = blk >> 5, gw = blk & 31;
    int d = threadIdx.x;

    __shared__ float as_[32][32];
    for (int i = d; i < 1024; i += 256) {
        int t = i >> 5, j = i & 31;
        as_[t][j] = att[(size_t)(b * Nn + t * 32 + gw) * 64 + 32 + j];
    }
    __syncthreads();

    float acc[32];
    #pragma unroll
    for (int t = 0; t < 32; t++) acc[t] = 0.f;

    #pragma unroll 4
    for (int j = 0; j < 32; j++) {
        float vj = qkv[(size_t)(b * Nn + j * 32 + gw) * QKVW + 64 + d];
        #pragma unroll
        for (int t = 0; t < 32; t++) acc[t] = fmaf(as_[t][j], vj, acc[t]);
    }
    float gm = gamma_all[layer];
    #pragma unroll
    for (int t = 0; t < 32; t++) {
        size_t idx = (size_t)(b * Nn + t * 32 + gw) * Dd + d;
        h[idx] += gm * acc[t];
    }
}

// ---------------------------------------------------------------------------
__global__ void head_k(const float* __restrict__ h, const float* __restrict__ w,
                       const float* __restrict__ bh, float* __restrict__ out)
{
    int m = blockIdx.x;
    int d = threadIdx.x;
    float p = h[(size_t)m * Dd + d] * w[d];
    #pragma unroll
    for (int o = 16; o > 0; o >>= 1) p += __shfl_xor_sync(0xFFFFFFFFu, p, o);
    __shared__ float s1[8];
    int lane = d & 31, wr = d >> 5;
    if (lane == 0) s1[wr] = p;
    __syncthreads();
    if (d == 0) {
        float S = 0;
        #pragma unroll
        for (int i = 0; i < 8; i++) S += s1[i];
        out[m] = S + bh[0];
    }
}

// ---------------------------------------------------------------------------
extern "C" void kernel_launch(void* const* d_in, const int* in_sizes, int n_in,
                              void* d_out, int out_size)
{
    const float* x       = (const float*)d_in[0];
    const float* w_patch = (const float*)d_in[1];
    const float* b_patch = (const float*)d_in[2];
    const float* pos     = (const float*)d_in[3];
    const float* w_edge  = (const float*)d_in[4];
    const float* b_edge  = (const float*)d_in[5];
    const float* ln_g    = (const float*)d_in[6];
    const float* ln_b    = (const float*)d_in[7];
    const float* wq      = (const float*)d_in[8];
    const float* bq      = (const float*)d_in[9];
    const float* wk      = (const float*)d_in[10];
    const float* bk      = (const float*)d_in[11];
    const float* wv      = (const float*)d_in[12];
    const float* bv      = (const float*)d_in[13];
    const float* gamma   = (const float*)d_in[14];
    const float* w1      = (const float*)d_in[15];
    const float* b1      = (const float*)d_in[16];
    const float* w2      = (const float*)d_in[17];
    const float* b2      = (const float*)d_in[18];
    const float* w_head  = (const float*)d_in[19];
    const float* b_head  = (const float*)d_in[20];
    float* out = (float*)d_out;

    float *h, *xn, *lap, *qkv, *mid, *att;
    float *wpT, *weT, *wqkvT, *bqkv, *w1T, *w2T;
    cudaGetSymbolAddress((void**)&h,     g_h);
    cudaGetSymbolAddress((void**)&xn,    g_xn);
    cudaGetSymbolAddress((void**)&lap,   g_lap);
    cudaGetSymbolAddress((void**)&qkv,   g_qkv);
    cudaGetSymbolAddress((void**)&mid,   g_mid);
    cudaGetSymbolAddress((void**)&att,   g_att);
    cudaGetSymbolAddress((void**)&wpT,   g_wpT);
    cudaGetSymbolAddress((void**)&weT,   g_weT);
    cudaGetSymbolAddress((void**)&wqkvT, g_wqkvT);
    cudaGetSymbolAddress((void**)&bqkv,  g_bqkv);
    cudaGetSymbolAddress((void**)&w1T,   g_w1T);
    cudaGetSymbolAddress((void**)&w2T,   g_w2T);

    const int SMEM = 2 * N_STAGES * T_STAGE * 4;   // 110592 bytes
    static bool attr_done = false;
    if (!attr_done) {
        cudaFuncSetAttribute(gemm_tc<0,1,0>, cudaFuncAttributeMaxDynamicSharedMemorySize, SMEM);
        cudaFuncSetAttribute(gemm_tc<1,1,1>, cudaFuncAttributeMaxDynamicSharedMemorySize, SMEM);
        cudaFuncSetAttribute(gemm_tc<2,0,0>, cudaFuncAttributeMaxDynamicSharedMemorySize, SMEM);
        cudaFuncSetAttribute(gemm_tc<3,1,0>, cudaFuncAttributeMaxDynamicSharedMemorySize, SMEM);
        cudaFuncSetAttribute(gemm_tc<4,0,0>, cudaFuncAttributeMaxDynamicSharedMemorySize, SMEM);
        attr_done = true;
    }

    const int M = Mtok;
    dim3 b256(256);

    // weight prep
    prep_all_k<<<2880, b256>>>(w_patch, w_edge, wq, wk, wv, bq, bk, bv,
                               wpT, weT, wqkvT, bqkv);
    transpose_big_k<<<dim3(32, 32, 16), b256>>>(w1, w2, w1T, w2T);

    // patch embed (im2col fused into A load)
    gemm_tc<1,1,1><<<dim3(2, M / 128), b256, SMEM>>>(x, wpT, b_patch, h, pos, M, Dd, Dd);

    // edge tokens: h += tanh(lap(h) @ w_edge + b_edge)
    lap_k<<<Mtok, b256>>>(h, lap);
    gemm_tc<2,0,0><<<dim3(2, M / 128), b256, SMEM>>>(lap, weT, b_edge, h, nullptr, M, Dd, Dd);

    for (int l = 0; l < 8; l++) {
        ln_k<<<Mtok / 8, b256>>>(h, xn, ln_g + l * Dd, ln_b + l * Dd);
        gemm_tc<0,1,0><<<dim3(3, M / 128), b256, SMEM>>>(xn, wqkvT + (size_t)l * QKVW * Dd,
                                                         bqkv + l * QKVW, qkv, nullptr, M, QKVW, Dd);
        attn_score_k<<<Mtok / 8, b256>>>(qkv, att);
        attn_apply_row_k<<<Mtok / 32, b256>>>(att, qkv, xn, h, gamma, l);
        attn_apply_col_k<<<Mtok / 32, b256>>>(att, qkv, h, gamma, l);

        ln_k<<<Mtok / 8, b256>>>(h, xn, ln_g + l * Dd, ln_b + l * Dd);
        gemm_tc<3,1,0><<<dim3(8, M / 128), b256, SMEM>>>(xn, w1T + (size_t)l * DFf * Dd,
                                                         b1 + l * DFf, mid, nullptr, M, DFf, Dd);
        gemm_tc<4,0,0><<<dim3(2, M / 128), b256, SMEM>>>(mid, w2T + (size_t)l * Dd * DFf,
                                                         b2 + l * Dd, h, nullptr, M, Dd, DFf);
    }

    head_k<<<Mtok, b256>>>(h, w_head, b_head, out);
}